// round 11
// baseline (speedup 1.0000x reference)
#include <cuda_runtime.h>
#include <cuda_fp16.h>
#include <math.h>

#define BB 8
#define CC 64
#define HH 128
#define WW 128
#define HW (HH*WW)
#define KK 9
#define CO 64
#define CK (CC*KK)   // 576

typedef unsigned int u32;

__device__ __half g_xth[BB*HW*CC];      // x NHWC fp16
__device__ float  g_off[BB*27*HW];      // planar offsets/masks
__device__ __half g_colb[(size_t)HW*CK];// single-batch col slice (18.9MB, L2-resident)
__device__ __half g_wth[KK*CO*CC];      // dcn weights [t][co][c] fp16
__device__ __half g_woh[KK*32*CC];      // offset weights [t][o pad32][c] fp16

#define CSTRH 72
#define TP 128

// ---------------------------------------------------------------------------
// Kernel A: NCHW -> NHWC transpose (fp16 output)
// ---------------------------------------------------------------------------
__global__ void k_transpose(const float* __restrict__ x) {
    __shared__ float tile[32][33];
    int b  = blockIdx.z;
    int p0 = blockIdx.x * 32;
    int c0 = blockIdx.y * 32;
    int tx = threadIdx.x, ty = threadIdx.y;   // 32 x 8
    const float* xb = x + (size_t)b * CC * HW;
    #pragma unroll
    for (int i = 0; i < 32; i += 8)
        tile[ty + i][tx] = xb[(size_t)(c0 + ty + i) * HW + p0 + tx];
    __syncthreads();
    __half* xoh = g_xth + (size_t)b * HW * CC;
    #pragma unroll
    for (int i = 0; i < 32; i += 8)
        xoh[(size_t)(p0 + ty + i) * CC + c0 + tx] = __float2half(tile[tx][ty + i]);
}

// ---------------------------------------------------------------------------
// Kernel W: weight reorder/convert
// ---------------------------------------------------------------------------
__global__ void k_wreorder(const float* __restrict__ wd, const float* __restrict__ wo) {
    int idx = blockIdx.x * 256 + threadIdx.x;
    if (idx < KK * CO * CC) {
        int t  = idx >> 12;
        int co = (idx >> 6) & 63;
        int c  = idx & 63;
        g_wth[idx] = __float2half(wd[co * CK + c * KK + t]);
    }
    if (idx < KK * 32 * CC) {
        int t = idx >> 11;
        int o = (idx >> 6) & 31;
        int c = idx & 63;
        g_woh[idx] = __float2half(o < 27 ? wo[o * CK + c * KK + t] : 0.f);
    }
}

// ---------------------------------------------------------------------------
// Kernel B: offset conv via tensor cores
// ---------------------------------------------------------------------------
__global__ void __launch_bounds__(256, 3) k_offcv(const float* __restrict__ b_off) {
    extern __shared__ __half smh[];
    __half* col = smh;                    // 128 * 72 halves
    __half* wsO = smh + 128 * CSTRH;      // 32 * 72 halves

    int tid = threadIdx.x;
    int b   = blockIdx.y;
    int p0  = blockIdx.x * 128;
    int ho  = blockIdx.x;

    int g = tid >> 3, lane8 = tid & 7, cbase = lane8 * 8;
    const __half* xb = g_xth + (size_t)b * HW * CC;

    int lane = tid & 31, w = tid >> 5;
    int cobase = (w & 1) * 16;
    int pxh    = (w >> 1) * 32;
    int gid = lane >> 2, tig = lane & 3;

    float bl = (cobase + gid     < 27) ? b_off[cobase + gid]     : 0.f;
    float bh = (cobase + gid + 8 < 27) ? b_off[cobase + gid + 8] : 0.f;
    float acc[4][4];
    #pragma unroll
    for (int nt = 0; nt < 4; nt++) {
        acc[nt][0] = bl; acc[nt][1] = bl;
        acc[nt][2] = bh; acc[nt][3] = bh;
    }

    #pragma unroll 1
    for (int t = 0; t < 9; t++) {
        const u32* wsrc = (const u32*)(g_woh + t * 32 * CC);
        #pragma unroll
        for (int idx = tid; idx < 1024; idx += 256) {
            int o = idx >> 5, kp = idx & 31;
            *(u32*)&wsO[o * CSTRH + kp * 2] = wsrc[idx];
        }

        int dty = t / 3 - 1, dtx = t % 3 - 1;
        int y = ho + dty;
        bool vy = (y >= 0) & (y < HH);
        #pragma unroll
        for (int pass = 0; pass < 4; pass++) {
            int pi = pass * 32 + g;
            int xx = pi + dtx;
            uint4 v = make_uint4(0, 0, 0, 0);
            if (vy & (xx >= 0) & (xx < WW))
                v = *(const uint4*)(xb + ((size_t)(y * WW + xx)) * CC + cbase);
            *(uint4*)&col[pi * CSTRH + cbase] = v;
        }
        __syncthreads();

        #pragma unroll
        for (int ks = 0; ks < 4; ks++) {
            int kb = ks * 16 + 2 * tig;
            u32 a0 = *(u32*)&wsO[(cobase + gid)     * CSTRH + kb];
            u32 a1 = *(u32*)&wsO[(cobase + gid + 8) * CSTRH + kb];
            u32 a2 = *(u32*)&wsO[(cobase + gid)     * CSTRH + kb + 8];
            u32 a3 = *(u32*)&wsO[(cobase + gid + 8) * CSTRH + kb + 8];
            #pragma unroll
            for (int nt = 0; nt < 4; nt++) {
                const __half* brow = &col[(pxh + nt * 8 + gid) * CSTRH + kb];
                u32 b0 = *(const u32*)brow;
                u32 b1 = *(const u32*)(brow + 8);
                asm volatile(
                    "mma.sync.aligned.m16n8k16.row.col.f32.f16.f16.f32 "
                    "{%0,%1,%2,%3}, {%4,%5,%6,%7}, {%8,%9}, {%0,%1,%2,%3};"
                    : "+f"(acc[nt][0]), "+f"(acc[nt][1]),
                      "+f"(acc[nt][2]), "+f"(acc[nt][3])
                    : "r"(a0), "r"(a1), "r"(a2), "r"(a3), "r"(b0), "r"(b1));
            }
        }
        __syncthreads();
    }

    float* ob = g_off + (size_t)b * 27 * HW;
    #pragma unroll
    for (int nt = 0; nt < 4; nt++) {
        int wo_lo = pxh + nt * 8 + 2 * tig;
        int p = p0 + wo_lo;
        #pragma unroll
        for (int j = 0; j < 2; j++) {
            int o = cobase + gid + j * 8;
            if (o >= 27) continue;
            float v0 = acc[nt][j * 2], v1 = acc[nt][j * 2 + 1];
            if (o < 9) {
                float a = (float)(ho + o / 3 - 1);
                v0 += a; v1 += a;
            } else if (o < 18) {
                int tt = o - 9;
                float a = (float)(wo_lo + tt % 3 - 1);
                v0 += a; v1 += a + 1.f;
            } else {
                v0 = 1.f / (1.f + __expf(-v0));
                v1 = 1.f / (1.f + __expf(-v1));
            }
            *(float2*)(ob + (size_t)o * HW + p) = make_float2(v0, v1);
        }
    }
}

// ---------------------------------------------------------------------------
// Kernel G: streaming bilinear gather for ONE batch -> g_colb (L2-resident)
// ---------------------------------------------------------------------------
__global__ void __launch_bounds__(256) k_gather(int b) {
    int tid = threadIdx.x;
    int p0  = blockIdx.x * 32;

    int g = tid >> 3, lane8 = tid & 7, cbase = lane8 * 8;
    int px = p0 + g;
    const __half* xb = g_xth + (size_t)b * HW * CC;
    const float* offb = g_off + (size_t)b * 27 * HW;
    __half* cdst = g_colb + (size_t)px * CK + cbase;

    #pragma unroll 3
    for (int t = 0; t < 9; t++) {
        float py  = offb[(size_t)t * HW + px];
        float pxs = offb[(size_t)(9 + t) * HW + px];
        float mm  = offb[(size_t)(18 + t) * HW + px];
        float y0f = floorf(py), x0f = floorf(pxs);
        float dy = py - y0f, dx = pxs - x0f;
        int y0 = (int)y0f, x0 = (int)x0f;
        int y1 = y0 + 1,  x1 = x0 + 1;
        float wy0 = ((y0 >= 0) & (y0 < HH)) ? (1.f - dy) * mm : 0.f;
        float wy1 = ((y1 >= 0) & (y1 < HH)) ? dy * mm : 0.f;
        float wx0 = ((x0 >= 0) & (x0 < WW)) ? (1.f - dx) : 0.f;
        float wx1 = ((x1 >= 0) & (x1 < WW)) ? dx : 0.f;
        float w00 = wy0 * wx0, w01 = wy0 * wx1;
        float w10 = wy1 * wx0, w11 = wy1 * wx1;
        int y0c = min(max(y0, 0), HH - 1), y1c = min(max(y1, 0), HH - 1);
        int x0c = min(max(x0, 0), WW - 1), x1c = min(max(x1, 0), WW - 1);

        uint4 v00 = *(const uint4*)(xb + ((size_t)(y0c * WW + x0c)) * CC + cbase);
        uint4 v01 = *(const uint4*)(xb + ((size_t)(y0c * WW + x1c)) * CC + cbase);
        uint4 v10 = *(const uint4*)(xb + ((size_t)(y1c * WW + x0c)) * CC + cbase);
        uint4 v11 = *(const uint4*)(xb + ((size_t)(y1c * WW + x1c)) * CC + cbase);
        const __half2* h00 = (const __half2*)&v00;
        const __half2* h01 = (const __half2*)&v01;
        const __half2* h10 = (const __half2*)&v10;
        const __half2* h11 = (const __half2*)&v11;

        __half2 hh[4];
        #pragma unroll
        for (int q = 0; q < 4; q++) {
            float2 f00 = __half22float2(h00[q]);
            float2 f01 = __half22float2(h01[q]);
            float2 f10 = __half22float2(h10[q]);
            float2 f11 = __half22float2(h11[q]);
            float rx = w00 * f00.x + w01 * f01.x + w10 * f10.x + w11 * f11.x;
            float ry = w00 * f00.y + w01 * f01.y + w10 * f10.y + w11 * f11.y;
            hh[q] = __floats2half2_rn(rx, ry);
        }
        *(uint4*)(cdst + t * 64) = *(uint4*)hh;
    }
}

// ---------------------------------------------------------------------------
// Kernel M: GEMM col[128px][576] x W[576][64] for ONE batch (col from L2).
// Tap chunk = 1024 uint4 -> 4 per thread: pi = flat>>3, grp = flat&7.
// ---------------------------------------------------------------------------
__global__ void __launch_bounds__(256, 3) k_gemm(const float* __restrict__ b_dcn,
                                                 float* __restrict__ out, int b) {
    extern __shared__ __half smh[];
    __half* cb[2] = { smh, smh + TP * CSTRH };
    __half* wb[2] = { smh + 2 * TP * CSTRH, smh + 2 * TP * CSTRH + CO * CSTRH };

    int tid = threadIdx.x;
    int p0  = blockIdx.x * TP;

    int lane = tid & 31, w = tid >> 5;
    int cobase = (w & 3) * 16;
    int pxh    = (w >> 2) * 64;
    int gid = lane >> 2, tig = lane & 3;

    const __half* csrc = g_colb + (size_t)p0 * CK;

    float acc[8][4];
    #pragma unroll
    for (int i = 0; i < 8; i++)
        #pragma unroll
        for (int j = 0; j < 4; j++) acc[i][j] = 0.f;

    // prologue: load tap 0 (col + weights) into buffer 0
    uint4 creg[4];
    #pragma unroll
    for (int i = 0; i < 4; i++) {
        int flat = i * 256 + tid;            // 0..1023
        int pi = flat >> 3, grp = flat & 7;  // pi 0..127, grp 0..7 (8 halves each)
        creg[i] = *(const uint4*)(csrc + (size_t)pi * CK + grp * 8);
        *(uint4*)&cb[0][pi * CSTRH + grp * 8] = creg[i];
    }
    {
        const u32* wsrc = (const u32*)(g_wth);
        #pragma unroll
        for (int idx = tid; idx < 2048; idx += 256) {
            int co = idx >> 5, kp = idx & 31;
            *(u32*)&wb[0][co * CSTRH + kp * 2] = wsrc[idx];
        }
    }
    __syncthreads();

    #pragma unroll 1
    for (int t = 0; t < 9; t++) {
        int cur = t & 1, nxt = cur ^ 1;

        if (t < 8) {
            #pragma unroll
            for (int i = 0; i < 4; i++) {
                int flat = i * 256 + tid;
                int pi = flat >> 3, grp = flat & 7;
                creg[i] = *(const uint4*)(csrc + (size_t)pi * CK + (t + 1) * 64 + grp * 8);
            }
            const u32* wsrc = (const u32*)(g_wth + (t + 1) * CO * CC);
            #pragma unroll
            for (int idx = tid; idx < 2048; idx += 256) {
                int co = idx >> 5, kp = idx & 31;
                *(u32*)&wb[nxt][co * CSTRH + kp * 2] = wsrc[idx];
            }
        }

        #pragma unroll
        for (int ks = 0; ks < 4; ks++) {
            int kb = ks * 16 + 2 * tig;
            u32 a0 = *(const u32*)&wb[cur][(cobase + gid)     * CSTRH + kb];
            u32 a1 = *(const u32*)&wb[cur][(cobase + gid + 8) * CSTRH + kb];
            u32 a2 = *(const u32*)&wb[cur][(cobase + gid)     * CSTRH + kb + 8];
            u32 a3 = *(const u32*)&wb[cur][(cobase + gid + 8) * CSTRH + kb + 8];
            #pragma unroll
            for (int nt = 0; nt < 8; nt++) {
                const __half* brow = &cb[cur][(pxh + nt * 8 + gid) * CSTRH + kb];
                u32 b0 = *(const u32*)brow;
                u32 b1 = *(const u32*)(brow + 8);
                asm volatile(
                    "mma.sync.aligned.m16n8k16.row.col.f32.f16.f16.f32 "
                    "{%0,%1,%2,%3}, {%4,%5,%6,%7}, {%8,%9}, {%0,%1,%2,%3};"
                    : "+f"(acc[nt][0]), "+f"(acc[nt][1]),
                      "+f"(acc[nt][2]), "+f"(acc[nt][3])
                    : "r"(a0), "r"(a1), "r"(a2), "r"(a3), "r"(b0), "r"(b1));
            }
        }

        if (t < 8) {
            #pragma unroll
            for (int i = 0; i < 4; i++) {
                int flat = i * 256 + tid;
                int pi = flat >> 3, grp = flat & 7;
                *(uint4*)&cb[nxt][pi * CSTRH + grp * 8] = creg[i];
            }
        }
        __syncthreads();
    }

    float bl = b_dcn[cobase + gid];
    float bh = b_dcn[cobase + gid + 8];
    float* ob = out + (size_t)b * CO * HW + p0 + pxh + 2 * tig;
    #pragma unroll
    for (int nt = 0; nt < 8; nt++) {
        float2 vlo = make_float2(acc[nt][0] + bl, acc[nt][1] + bl);
        float2 vhi = make_float2(acc[nt][2] + bh, acc[nt][3] + bh);
        *(float2*)(ob + (size_t)(cobase + gid)     * HW + nt * 8) = vlo;
        *(float2*)(ob + (size_t)(cobase + gid + 8) * HW + nt * 8) = vhi;
    }
}

// ---------------------------------------------------------------------------
extern "C" void kernel_launch(void* const* d_in, const int* in_sizes, int n_in,
                              void* d_out, int out_size) {
    const float* x        = (const float*)d_in[0];
    const float* w_offset = (const float*)d_in[1];
    const float* b_offset = (const float*)d_in[2];
    const float* w_dcn    = (const float*)d_in[3];
    const float* b_dcn    = (const float*)d_in[4];
    float* out = (float*)d_out;

    const int SMEM_O = (128 * CSTRH + 32 * CSTRH) * 2;             // 23040
    const int SMEM_M = (2 * TP * CSTRH + 2 * CO * CSTRH) * 2;      // 55296
    cudaFuncSetAttribute(k_offcv, cudaFuncAttributeMaxDynamicSharedMemorySize, SMEM_O);
    cudaFuncSetAttribute(k_gemm,  cudaFuncAttributeMaxDynamicSharedMemorySize, SMEM_M);

    k_transpose<<<dim3(HW / 32, CC / 32, BB), dim3(32, 8)>>>(x);
    k_wreorder<<<(KK * CO * CC + 255) / 256, 256>>>(w_dcn, w_offset);
    k_offcv<<<dim3(HW / 128, BB), 256, SMEM_O>>>(b_offset);
    for (int b = 0; b < BB; b++) {
        k_gather<<<HW / 32, 256>>>(b);
        k_gemm<<<HW / TP, 256, SMEM_M>>>(b_dcn, out, b);
    }
}

// round 12
// speedup vs baseline: 2.2016x; 2.2016x over previous
#include <cuda_runtime.h>
#include <cuda_fp16.h>
#include <math.h>

#define BB 8
#define CC 64
#define HH 128
#define WW 128
#define HW (HH*WW)
#define KK 9
#define CO 64
#define CK (CC*KK)   // 576

typedef unsigned int u32;

__device__ __half g_xth[BB*HW*CC];      // x NHWC fp16
__device__ float  g_off[BB*27*HW];      // planar offsets/masks
__device__ __half g_wth[KK*CO*CC];      // dcn weights [t][co][c] fp16
__device__ __half g_woh[KK*32*CC];      // offset weights [t][o pad32][c] fp16

#define CSTRH 72
#define TP 128

__device__ __forceinline__ void cp16(u32 dst_smem, const void* src) {
    asm volatile("cp.async.cg.shared.global [%0], [%1], 16;"
                 :: "r"(dst_smem), "l"(src) : "memory");
}

// ---------------------------------------------------------------------------
// Kernel A: NCHW -> NHWC transpose (fp16 output)
// ---------------------------------------------------------------------------
__global__ void k_transpose(const float* __restrict__ x) {
    __shared__ float tile[32][33];
    int b  = blockIdx.z;
    int p0 = blockIdx.x * 32;
    int c0 = blockIdx.y * 32;
    int tx = threadIdx.x, ty = threadIdx.y;   // 32 x 8
    const float* xb = x + (size_t)b * CC * HW;
    #pragma unroll
    for (int i = 0; i < 32; i += 8)
        tile[ty + i][tx] = xb[(size_t)(c0 + ty + i) * HW + p0 + tx];
    __syncthreads();
    __half* xoh = g_xth + (size_t)b * HW * CC;
    #pragma unroll
    for (int i = 0; i < 32; i += 8)
        xoh[(size_t)(p0 + ty + i) * CC + c0 + tx] = __float2half(tile[tx][ty + i]);
}

// ---------------------------------------------------------------------------
// Kernel W: weight reorder/convert
// ---------------------------------------------------------------------------
__global__ void k_wreorder(const float* __restrict__ wd, const float* __restrict__ wo) {
    int idx = blockIdx.x * 256 + threadIdx.x;
    if (idx < KK * CO * CC) {
        int t  = idx >> 12;
        int co = (idx >> 6) & 63;
        int c  = idx & 63;
        g_wth[idx] = __float2half(wd[co * CK + c * KK + t]);
    }
    if (idx < KK * 32 * CC) {
        int t = idx >> 11;
        int o = (idx >> 6) & 31;
        int c = idx & 63;
        g_woh[idx] = __float2half(o < 27 ? wo[o * CK + c * KK + t] : 0.f);
    }
}

// ---------------------------------------------------------------------------
// Kernel B: offset conv via tensor cores
// ---------------------------------------------------------------------------
__global__ void __launch_bounds__(256, 3) k_offcv(const float* __restrict__ b_off) {
    extern __shared__ __half smh[];
    __half* col = smh;                    // 128 * 72 halves
    __half* wsO = smh + 128 * CSTRH;      // 32 * 72 halves

    int tid = threadIdx.x;
    int b   = blockIdx.y;
    int p0  = blockIdx.x * 128;
    int ho  = blockIdx.x;

    int g = tid >> 3, lane8 = tid & 7, cbase = lane8 * 8;
    const __half* xb = g_xth + (size_t)b * HW * CC;

    int lane = tid & 31, w = tid >> 5;
    int cobase = (w & 1) * 16;
    int pxh    = (w >> 1) * 32;
    int gid = lane >> 2, tig = lane & 3;

    float bl = (cobase + gid     < 27) ? b_off[cobase + gid]     : 0.f;
    float bh = (cobase + gid + 8 < 27) ? b_off[cobase + gid + 8] : 0.f;
    float acc[4][4];
    #pragma unroll
    for (int nt = 0; nt < 4; nt++) {
        acc[nt][0] = bl; acc[nt][1] = bl;
        acc[nt][2] = bh; acc[nt][3] = bh;
    }

    #pragma unroll 1
    for (int t = 0; t < 9; t++) {
        const u32* wsrc = (const u32*)(g_woh + t * 32 * CC);
        #pragma unroll
        for (int idx = tid; idx < 1024; idx += 256) {
            int o = idx >> 5, kp = idx & 31;
            *(u32*)&wsO[o * CSTRH + kp * 2] = wsrc[idx];
        }

        int dty = t / 3 - 1, dtx = t % 3 - 1;
        int y = ho + dty;
        bool vy = (y >= 0) & (y < HH);
        #pragma unroll
        for (int pass = 0; pass < 4; pass++) {
            int pi = pass * 32 + g;
            int xx = pi + dtx;
            uint4 v = make_uint4(0, 0, 0, 0);
            if (vy & (xx >= 0) & (xx < WW))
                v = *(const uint4*)(xb + ((size_t)(y * WW + xx)) * CC + cbase);
            *(uint4*)&col[pi * CSTRH + cbase] = v;
        }
        __syncthreads();

        #pragma unroll
        for (int ks = 0; ks < 4; ks++) {
            int kb = ks * 16 + 2 * tig;
            u32 a0 = *(u32*)&wsO[(cobase + gid)     * CSTRH + kb];
            u32 a1 = *(u32*)&wsO[(cobase + gid + 8) * CSTRH + kb];
            u32 a2 = *(u32*)&wsO[(cobase + gid)     * CSTRH + kb + 8];
            u32 a3 = *(u32*)&wsO[(cobase + gid + 8) * CSTRH + kb + 8];
            #pragma unroll
            for (int nt = 0; nt < 4; nt++) {
                const __half* brow = &col[(pxh + nt * 8 + gid) * CSTRH + kb];
                u32 b0 = *(const u32*)brow;
                u32 b1 = *(const u32*)(brow + 8);
                asm volatile(
                    "mma.sync.aligned.m16n8k16.row.col.f32.f16.f16.f32 "
                    "{%0,%1,%2,%3}, {%4,%5,%6,%7}, {%8,%9}, {%0,%1,%2,%3};"
                    : "+f"(acc[nt][0]), "+f"(acc[nt][1]),
                      "+f"(acc[nt][2]), "+f"(acc[nt][3])
                    : "r"(a0), "r"(a1), "r"(a2), "r"(a3), "r"(b0), "r"(b1));
            }
        }
        __syncthreads();
    }

    float* ob = g_off + (size_t)b * 27 * HW;
    #pragma unroll
    for (int nt = 0; nt < 4; nt++) {
        int wo_lo = pxh + nt * 8 + 2 * tig;
        int p = p0 + wo_lo;
        #pragma unroll
        for (int j = 0; j < 2; j++) {
            int o = cobase + gid + j * 8;
            if (o >= 27) continue;
            float v0 = acc[nt][j * 2], v1 = acc[nt][j * 2 + 1];
            if (o < 9) {
                float a = (float)(ho + o / 3 - 1);
                v0 += a; v1 += a;
            } else if (o < 18) {
                int tt = o - 9;
                float a = (float)(wo_lo + tt % 3 - 1);
                v0 += a; v1 += a + 1.f;
            } else {
                v0 = 1.f / (1.f + __expf(-v0));
                v1 = 1.f / (1.f + __expf(-v1));
            }
            *(float2*)(ob + (size_t)o * HW + p) = make_float2(v0, v1);
        }
    }
}

// ---------------------------------------------------------------------------
// k_dcn helpers
// ---------------------------------------------------------------------------
__device__ __forceinline__ void gather_issue(
        const __half* __restrict__ xb, const float* __restrict__ soff,
        int t, int pi, int cbase,
        uint4& v00, uint4& v01, uint4& v10, uint4& v11,
        float& w00, float& w01, float& w10, float& w11) {
    float py  = soff[t * TP + pi];
    float pxs = soff[(9 + t) * TP + pi];
    float mm  = soff[(18 + t) * TP + pi];
    float y0f = floorf(py), x0f = floorf(pxs);
    float dy = py - y0f, dx = pxs - x0f;
    int y0 = (int)y0f, x0 = (int)x0f;
    int y1 = y0 + 1,  x1 = x0 + 1;
    float wy0 = ((y0 >= 0) & (y0 < HH)) ? (1.f - dy) * mm : 0.f;
    float wy1 = ((y1 >= 0) & (y1 < HH)) ? dy * mm : 0.f;
    float wx0 = ((x0 >= 0) & (x0 < WW)) ? (1.f - dx) : 0.f;
    float wx1 = ((x1 >= 0) & (x1 < WW)) ? dx : 0.f;
    w00 = wy0 * wx0; w01 = wy0 * wx1;
    w10 = wy1 * wx0; w11 = wy1 * wx1;
    int y0c = min(max(y0, 0), HH - 1), y1c = min(max(y1, 0), HH - 1);
    int x0c = min(max(x0, 0), WW - 1), x1c = min(max(x1, 0), WW - 1);
    v00 = *(const uint4*)(xb + ((size_t)(y0c * WW + x0c)) * CC + cbase);
    v01 = *(const uint4*)(xb + ((size_t)(y0c * WW + x1c)) * CC + cbase);
    v10 = *(const uint4*)(xb + ((size_t)(y1c * WW + x0c)) * CC + cbase);
    v11 = *(const uint4*)(xb + ((size_t)(y1c * WW + x1c)) * CC + cbase);
}

__device__ __forceinline__ void gather_combine(
        __half* __restrict__ cbuf, int pi, int cbase,
        const uint4& v00, const uint4& v01, const uint4& v10, const uint4& v11,
        float w00, float w01, float w10, float w11) {
    const __half2* h00 = (const __half2*)&v00;
    const __half2* h01 = (const __half2*)&v01;
    const __half2* h10 = (const __half2*)&v10;
    const __half2* h11 = (const __half2*)&v11;
    __half2 hh[4];
    #pragma unroll
    for (int q = 0; q < 4; q++) {
        float2 f00 = __half22float2(h00[q]);
        float2 f01 = __half22float2(h01[q]);
        float2 f10 = __half22float2(h10[q]);
        float2 f11 = __half22float2(h11[q]);
        float rx = w00 * f00.x + w01 * f01.x + w10 * f10.x + w11 * f11.x;
        float ry = w00 * f00.y + w01 * f01.y + w10 * f10.y + w11 * f11.y;
        hh[q] = __floats2half2_rn(rx, ry);
    }
    *(uint4*)&cbuf[pi * CSTRH + cbase] = *(uint4*)hh;
}

__device__ __forceinline__ void mma_ks(
        const __half* __restrict__ col, const __half* __restrict__ wsT,
        float (&acc)[8][4], int ks, int cobase, int pxh, int gid, int tig) {
    int kb = ks * 16 + 2 * tig;
    u32 a0 = *(const u32*)&wsT[(cobase + gid)     * CSTRH + kb];
    u32 a1 = *(const u32*)&wsT[(cobase + gid + 8) * CSTRH + kb];
    u32 a2 = *(const u32*)&wsT[(cobase + gid)     * CSTRH + kb + 8];
    u32 a3 = *(const u32*)&wsT[(cobase + gid + 8) * CSTRH + kb + 8];
    #pragma unroll
    for (int nt = 0; nt < 8; nt++) {
        const __half* brow = &col[(pxh + nt * 8 + gid) * CSTRH + kb];
        u32 b0 = *(const u32*)brow;
        u32 b1 = *(const u32*)(brow + 8);
        asm volatile(
            "mma.sync.aligned.m16n8k16.row.col.f32.f16.f16.f32 "
            "{%0,%1,%2,%3}, {%4,%5,%6,%7}, {%8,%9}, {%0,%1,%2,%3};"
            : "+f"(acc[nt][0]), "+f"(acc[nt][1]),
              "+f"(acc[nt][2]), "+f"(acc[nt][3])
            : "r"(a0), "r"(a1), "r"(a2), "r"(a3), "r"(b0), "r"(b1));
    }
}

__device__ __forceinline__ void stage_w_async(__half* wbuf, int t, int tid) {
    u32 wbs = (u32)__cvta_generic_to_shared(wbuf);
    const __half* wsrc = g_wth + t * CO * CC;
    #pragma unroll
    for (int i = 0; i < 2; i++) {
        int idx = i * 256 + tid;          // 0..511
        int co = idx >> 3, kp8 = idx & 7; // 16B = 8 halves per cp
        cp16(wbs + (co * CSTRH + kp8 * 8) * 2, wsrc + co * CC + kp8 * 8);
    }
    asm volatile("cp.async.commit_group;" ::: "memory");
}

// ---------------------------------------------------------------------------
// Kernel C: fused gather+GEMM with intra-tap interleaving.
// Per tap, per pass: issue tap t+1 corner LDGs -> MMA chunk on tap t ->
// combine+STS. Offsets live in smem; weights staged by cp.async.
// ---------------------------------------------------------------------------
__global__ void __launch_bounds__(256, 3) k_dcn(const float* __restrict__ b_dcn,
                                                float* __restrict__ out) {
    extern __shared__ __half smh[];
    __half* cb[2] = { smh, smh + TP * CSTRH };
    __half* wb[2] = { smh + 2 * TP * CSTRH, smh + 2 * TP * CSTRH + CO * CSTRH };
    float*  soff  = (float*)(smh + 2 * TP * CSTRH + 2 * CO * CSTRH);  // [27][TP]

    int tid = threadIdx.x;
    int b   = blockIdx.y;
    int p0  = blockIdx.x * TP;

    int g = tid >> 3, lane8 = tid & 7, cbase = lane8 * 8;
    const __half* xb = g_xth + (size_t)b * HW * CC;
    const float* offb = g_off + (size_t)b * 27 * HW;

    int lane = tid & 31, w = tid >> 5;
    int cobase = (w & 3) * 16;
    int pxh    = (w >> 2) * 64;
    int gid = lane >> 2, tig = lane & 3;

    // preload offsets to smem (plane-major, coalesced)
    #pragma unroll
    for (int i = tid; i < 27 * TP; i += 256)
        soff[i] = offb[(size_t)(i >> 7) * HW + p0 + (i & 127)];

    stage_w_async(wb[0], 0, tid);
    asm volatile("cp.async.wait_group 0;" ::: "memory");
    __syncthreads();                       // soff + wb[0] ready

    // prologue: gather tap 0 into cb[0]
    #pragma unroll
    for (int pass = 0; pass < 4; pass++) {
        int pi = pass * 32 + g;
        uint4 v00, v01, v10, v11;
        float w00, w01, w10, w11;
        gather_issue(xb, soff, 0, pi, cbase, v00, v01, v10, v11, w00, w01, w10, w11);
        gather_combine(cb[0], pi, cbase, v00, v01, v10, v11, w00, w01, w10, w11);
    }
    __syncthreads();

    float acc[8][4];
    #pragma unroll
    for (int i = 0; i < 8; i++)
        #pragma unroll
        for (int j = 0; j < 4; j++) acc[i][j] = 0.f;

    #pragma unroll 1
    for (int t = 0; t < 8; t++) {
        int cur = t & 1, nxt = cur ^ 1;

        stage_w_async(wb[nxt], t + 1, tid);   // weights fly all tap

        #pragma unroll
        for (int pass = 0; pass < 4; pass++) {
            int pi = pass * 32 + g;
            uint4 v00, v01, v10, v11;
            float w00, w01, w10, w11;
            // 1. issue tap t+1 corner LDGs (no wait)
            gather_issue(xb, soff, t + 1, pi, cbase,
                         v00, v01, v10, v11, w00, w01, w10, w11);
            // 2. MMA chunk on tap t (hides the LDG latency)
            mma_ks(cb[cur], wb[cur], acc, pass, cobase, pxh, gid, tig);
            // 3. combine arrived corners -> col buffer for t+1
            gather_combine(cb[nxt], pi, cbase,
                           v00, v01, v10, v11, w00, w01, w10, w11);
        }

        asm volatile("cp.async.wait_group 0;" ::: "memory");
        __syncthreads();
    }

    // final tap 8: MMA only (cur = 0)
    #pragma unroll
    for (int pass = 0; pass < 4; pass++)
        mma_ks(cb[0], wb[0], acc, pass, cobase, pxh, gid, tig);

    float bl = b_dcn[cobase + gid];
    float bh = b_dcn[cobase + gid + 8];
    float* ob = out + (size_t)b * CO * HW + p0 + pxh + 2 * tig;
    #pragma unroll
    for (int nt = 0; nt < 8; nt++) {
        float2 vlo = make_float2(acc[nt][0] + bl, acc[nt][1] + bl);
        float2 vhi = make_float2(acc[nt][2] + bh, acc[nt][3] + bh);
        *(float2*)(ob + (size_t)(cobase + gid)     * HW + nt * 8) = vlo;
        *(float2*)(ob + (size_t)(cobase + gid + 8) * HW + nt * 8) = vhi;
    }
}

// ---------------------------------------------------------------------------
extern "C" void kernel_launch(void* const* d_in, const int* in_sizes, int n_in,
                              void* d_out, int out_size) {
    const float* x        = (const float*)d_in[0];
    const float* w_offset = (const float*)d_in[1];
    const float* b_offset = (const float*)d_in[2];
    const float* w_dcn    = (const float*)d_in[3];
    const float* b_dcn    = (const float*)d_in[4];
    float* out = (float*)d_out;

    const int SMEM_O = (128 * CSTRH + 32 * CSTRH) * 2;                       // 23040
    const int SMEM_C = (2 * TP * CSTRH + 2 * CO * CSTRH) * 2 + 27 * TP * 4;  // 69120
    cudaFuncSetAttribute(k_offcv, cudaFuncAttributeMaxDynamicSharedMemorySize, SMEM_O);
    cudaFuncSetAttribute(k_dcn,   cudaFuncAttributeMaxDynamicSharedMemorySize, SMEM_C);

    k_transpose<<<dim3(HW / 32, CC / 32, BB), dim3(32, 8)>>>(x);
    k_wreorder<<<(KK * CO * CC + 255) / 256, 256>>>(w_dcn, w_offset);
    k_offcv<<<dim3(HW / 128, BB), 256, SMEM_O>>>(b_offset);
    k_dcn<<<dim3(HW / TP, BB), 256, SMEM_C>>>(b_dcn, out);
}

// round 13
// speedup vs baseline: 2.2950x; 1.0424x over previous
#include <cuda_runtime.h>
#include <cuda_fp16.h>
#include <math.h>

#define BB 8
#define CC 64
#define HH 128
#define WW 128
#define HW (HH*WW)
#define KK 9
#define CO 64
#define CK (CC*KK)   // 576

typedef unsigned int u32;

__device__ __half g_xth[BB*HW*CC];      // x NHWC fp16
__device__ float  g_off[BB*27*HW];      // planar offsets/masks
__device__ __half g_wth[KK*CO*CC];      // dcn weights [t][co][c] fp16
__device__ __half g_woh[KK*32*CC];      // offset weights [t][o pad32][c] fp16

#define CSTRH 72
#define TP 128

__device__ __forceinline__ void cp16(u32 dst_smem, const void* src) {
    asm volatile("cp.async.cg.shared.global [%0], [%1], 16;"
                 :: "r"(dst_smem), "l"(src) : "memory");
}

// ---------------------------------------------------------------------------
// Kernel A: NCHW -> NHWC transpose (fp16 output)
// ---------------------------------------------------------------------------
__global__ void k_transpose(const float* __restrict__ x) {
    __shared__ float tile[32][33];
    int b  = blockIdx.z;
    int p0 = blockIdx.x * 32;
    int c0 = blockIdx.y * 32;
    int tx = threadIdx.x, ty = threadIdx.y;   // 32 x 8
    const float* xb = x + (size_t)b * CC * HW;
    #pragma unroll
    for (int i = 0; i < 32; i += 8)
        tile[ty + i][tx] = xb[(size_t)(c0 + ty + i) * HW + p0 + tx];
    __syncthreads();
    __half* xoh = g_xth + (size_t)b * HW * CC;
    #pragma unroll
    for (int i = 0; i < 32; i += 8)
        xoh[(size_t)(p0 + ty + i) * CC + c0 + tx] = __float2half(tile[tx][ty + i]);
}

// ---------------------------------------------------------------------------
// Kernel W: weight reorder/convert
// ---------------------------------------------------------------------------
__global__ void k_wreorder(const float* __restrict__ wd, const float* __restrict__ wo) {
    int idx = blockIdx.x * 256 + threadIdx.x;
    if (idx < KK * CO * CC) {
        int t  = idx >> 12;
        int co = (idx >> 6) & 63;
        int c  = idx & 63;
        g_wth[idx] = __float2half(wd[co * CK + c * KK + t]);
    }
    if (idx < KK * 32 * CC) {
        int t = idx >> 11;
        int o = (idx >> 6) & 31;
        int c = idx & 63;
        g_woh[idx] = __float2half(o < 27 ? wo[o * CK + c * KK + t] : 0.f);
    }
}

// ---------------------------------------------------------------------------
// Kernel B: offset conv via tensor cores
// ---------------------------------------------------------------------------
__global__ void __launch_bounds__(256, 3) k_offcv(const float* __restrict__ b_off) {
    extern __shared__ __half smh[];
    __half* col = smh;                    // 128 * 72 halves
    __half* wsO = smh + 128 * CSTRH;      // 32 * 72 halves

    int tid = threadIdx.x;
    int b   = blockIdx.y;
    int p0  = blockIdx.x * 128;
    int ho  = blockIdx.x;

    int g = tid >> 3, lane8 = tid & 7, cbase = lane8 * 8;
    const __half* xb = g_xth + (size_t)b * HW * CC;

    int lane = tid & 31, w = tid >> 5;
    int cobase = (w & 1) * 16;
    int pxh    = (w >> 1) * 32;
    int gid = lane >> 2, tig = lane & 3;

    float bl = (cobase + gid     < 27) ? b_off[cobase + gid]     : 0.f;
    float bh = (cobase + gid + 8 < 27) ? b_off[cobase + gid + 8] : 0.f;
    float acc[4][4];
    #pragma unroll
    for (int nt = 0; nt < 4; nt++) {
        acc[nt][0] = bl; acc[nt][1] = bl;
        acc[nt][2] = bh; acc[nt][3] = bh;
    }

    #pragma unroll 1
    for (int t = 0; t < 9; t++) {
        const u32* wsrc = (const u32*)(g_woh + t * 32 * CC);
        #pragma unroll
        for (int idx = tid; idx < 1024; idx += 256) {
            int o = idx >> 5, kp = idx & 31;
            *(u32*)&wsO[o * CSTRH + kp * 2] = wsrc[idx];
        }

        int dty = t / 3 - 1, dtx = t % 3 - 1;
        int y = ho + dty;
        bool vy = (y >= 0) & (y < HH);
        #pragma unroll
        for (int pass = 0; pass < 4; pass++) {
            int pi = pass * 32 + g;
            int xx = pi + dtx;
            uint4 v = make_uint4(0, 0, 0, 0);
            if (vy & (xx >= 0) & (xx < WW))
                v = *(const uint4*)(xb + ((size_t)(y * WW + xx)) * CC + cbase);
            *(uint4*)&col[pi * CSTRH + cbase] = v;
        }
        __syncthreads();

        #pragma unroll
        for (int ks = 0; ks < 4; ks++) {
            int kb = ks * 16 + 2 * tig;
            u32 a0 = *(u32*)&wsO[(cobase + gid)     * CSTRH + kb];
            u32 a1 = *(u32*)&wsO[(cobase + gid + 8) * CSTRH + kb];
            u32 a2 = *(u32*)&wsO[(cobase + gid)     * CSTRH + kb + 8];
            u32 a3 = *(u32*)&wsO[(cobase + gid + 8) * CSTRH + kb + 8];
            #pragma unroll
            for (int nt = 0; nt < 4; nt++) {
                const __half* brow = &col[(pxh + nt * 8 + gid) * CSTRH + kb];
                u32 b0 = *(const u32*)brow;
                u32 b1 = *(const u32*)(brow + 8);
                asm volatile(
                    "mma.sync.aligned.m16n8k16.row.col.f32.f16.f16.f32 "
                    "{%0,%1,%2,%3}, {%4,%5,%6,%7}, {%8,%9}, {%0,%1,%2,%3};"
                    : "+f"(acc[nt][0]), "+f"(acc[nt][1]),
                      "+f"(acc[nt][2]), "+f"(acc[nt][3])
                    : "r"(a0), "r"(a1), "r"(a2), "r"(a3), "r"(b0), "r"(b1));
            }
        }
        __syncthreads();
    }

    float* ob = g_off + (size_t)b * 27 * HW;
    #pragma unroll
    for (int nt = 0; nt < 4; nt++) {
        int wo_lo = pxh + nt * 8 + 2 * tig;
        int p = p0 + wo_lo;
        #pragma unroll
        for (int j = 0; j < 2; j++) {
            int o = cobase + gid + j * 8;
            if (o >= 27) continue;
            float v0 = acc[nt][j * 2], v1 = acc[nt][j * 2 + 1];
            if (o < 9) {
                float a = (float)(ho + o / 3 - 1);
                v0 += a; v1 += a;
            } else if (o < 18) {
                int tt = o - 9;
                float a = (float)(wo_lo + tt % 3 - 1);
                v0 += a; v1 += a + 1.f;
            } else {
                v0 = 1.f / (1.f + __expf(-v0));
                v1 = 1.f / (1.f + __expf(-v1));
            }
            *(float2*)(ob + (size_t)o * HW + p) = make_float2(v0, v1);
        }
    }
}

// ---------------------------------------------------------------------------
// k_dcn helpers
// ---------------------------------------------------------------------------
__device__ __forceinline__ void gather_issue(
        const __half* __restrict__ xb,
        const u32* __restrict__ dw0, const u32* __restrict__ dw1,
        const u32* __restrict__ dbase,
        int t, int pi, int cbase,
        uint4& v00, uint4& v01, uint4& v10, uint4& v11,
        u32& wA, u32& wB) {
    int it = t * TP + pi;
    u32 pk = dbase[it];
    wA = dw0[it];
    wB = dw1[it];
    int p00 = pk & 0x3FFF;
    int dxc = (pk >> 16) & 1;
    int dyc = (pk >> 17) & 1;
    const __half* b00 = xb + (size_t)p00 * CC + cbase;
    v00 = *(const uint4*)b00;
    v01 = *(const uint4*)(b00 + dxc * CC);
    v10 = *(const uint4*)(b00 + dyc * (WW * CC));
    v11 = *(const uint4*)(b00 + dyc * (WW * CC) + dxc * CC);
}

__device__ __forceinline__ void gather_combine(
        __half* __restrict__ cbuf, int pi, int cbase,
        const uint4& v00, const uint4& v01, const uint4& v10, const uint4& v11,
        u32 wA, u32 wB) {
    float2 fa = __half22float2(*(const __half2*)&wA);  // w00, w01
    float2 fb = __half22float2(*(const __half2*)&wB);  // w10, w11
    float w00 = fa.x, w01 = fa.y, w10 = fb.x, w11 = fb.y;
    const __half2* h00 = (const __half2*)&v00;
    const __half2* h01 = (const __half2*)&v01;
    const __half2* h10 = (const __half2*)&v10;
    const __half2* h11 = (const __half2*)&v11;
    __half2 hh[4];
    #pragma unroll
    for (int q = 0; q < 4; q++) {
        float2 f00 = __half22float2(h00[q]);
        float2 f01 = __half22float2(h01[q]);
        float2 f10 = __half22float2(h10[q]);
        float2 f11 = __half22float2(h11[q]);
        float rx = w00 * f00.x + w01 * f01.x + w10 * f10.x + w11 * f11.x;
        float ry = w00 * f00.y + w01 * f01.y + w10 * f10.y + w11 * f11.y;
        hh[q] = __floats2half2_rn(rx, ry);
    }
    *(uint4*)&cbuf[pi * CSTRH + cbase] = *(uint4*)hh;
}

__device__ __forceinline__ void mma_ks(
        const __half* __restrict__ col, const __half* __restrict__ wsT,
        float (&acc)[8][4], int ks, int cobase, int pxh, int gid, int tig) {
    int kb = ks * 16 + 2 * tig;
    u32 a0 = *(const u32*)&wsT[(cobase + gid)     * CSTRH + kb];
    u32 a1 = *(const u32*)&wsT[(cobase + gid + 8) * CSTRH + kb];
    u32 a2 = *(const u32*)&wsT[(cobase + gid)     * CSTRH + kb + 8];
    u32 a3 = *(const u32*)&wsT[(cobase + gid + 8) * CSTRH + kb + 8];
    #pragma unroll
    for (int nt = 0; nt < 8; nt++) {
        const __half* brow = &col[(pxh + nt * 8 + gid) * CSTRH + kb];
        u32 b0 = *(const u32*)brow;
        u32 b1 = *(const u32*)(brow + 8);
        asm volatile(
            "mma.sync.aligned.m16n8k16.row.col.f32.f16.f16.f32 "
            "{%0,%1,%2,%3}, {%4,%5,%6,%7}, {%8,%9}, {%0,%1,%2,%3};"
            : "+f"(acc[nt][0]), "+f"(acc[nt][1]),
              "+f"(acc[nt][2]), "+f"(acc[nt][3])
            : "r"(a0), "r"(a1), "r"(a2), "r"(a3), "r"(b0), "r"(b1));
    }
}

__device__ __forceinline__ void stage_w_async(__half* wbuf, int t, int tid) {
    u32 wbs = (u32)__cvta_generic_to_shared(wbuf);
    const __half* wsrc = g_wth + t * CO * CC;
    #pragma unroll
    for (int i = 0; i < 2; i++) {
        int idx = i * 256 + tid;          // 0..511
        int co = idx >> 3, kp8 = idx & 7; // 16B = 8 halves per cp
        cp16(wbs + (co * CSTRH + kp8 * 8) * 2, wsrc + co * CC + kp8 * 8);
    }
    asm volatile("cp.async.commit_group;" ::: "memory");
}

// ---------------------------------------------------------------------------
// Kernel C: fused gather+GEMM, intra-tap interleaved, with CTA-cooperative
// gather-descriptor precompute (no redundant per-lane coord math).
// desc per (t, pi): dw0 = half2(w00,w01), dw1 = half2(w10,w11),
//                   dbase = p00 | dx<<16 | dy<<17 (clamped, validity folded)
// ---------------------------------------------------------------------------
__global__ void __launch_bounds__(256, 3) k_dcn(const float* __restrict__ b_dcn,
                                                float* __restrict__ out) {
    extern __shared__ __half smh[];
    __half* cb[2] = { smh, smh + TP * CSTRH };
    __half* wb[2] = { smh + 2 * TP * CSTRH, smh + 2 * TP * CSTRH + CO * CSTRH };
    u32* dw0   = (u32*)(smh + 2 * TP * CSTRH + 2 * CO * CSTRH);  // [9*TP]
    u32* dw1   = dw0 + 9 * TP;
    u32* dbase = dw1 + 9 * TP;

    int tid = threadIdx.x;
    int b   = blockIdx.y;
    int p0  = blockIdx.x * TP;

    int g = tid >> 3, lane8 = tid & 7, cbase = lane8 * 8;
    const __half* xb = g_xth + (size_t)b * HW * CC;
    const float* offb = g_off + (size_t)b * 27 * HW;

    int lane = tid & 31, w = tid >> 5;
    int cobase = (w & 3) * 16;
    int pxh    = (w >> 2) * 64;
    int gid = lane >> 2, tig = lane & 3;

    stage_w_async(wb[0], 0, tid);

    // cooperative descriptor precompute: 1152 items, no per-lane redundancy
    #pragma unroll
    for (int i = tid; i < 9 * TP; i += 256) {
        int t = i >> 7, pi = i & 127;
        float py  = offb[(size_t)t * HW + p0 + pi];
        float pxs = offb[(size_t)(9 + t) * HW + p0 + pi];
        float mm  = offb[(size_t)(18 + t) * HW + p0 + pi];
        float y0f = floorf(py), x0f = floorf(pxs);
        float dy = py - y0f, dx = pxs - x0f;
        int y0 = (int)y0f, x0 = (int)x0f;
        int y1 = y0 + 1,  x1 = x0 + 1;
        float wy0 = ((y0 >= 0) & (y0 < HH)) ? (1.f - dy) * mm : 0.f;
        float wy1 = ((y1 >= 0) & (y1 < HH)) ? dy * mm : 0.f;
        float wx0 = ((x0 >= 0) & (x0 < WW)) ? (1.f - dx) : 0.f;
        float wx1 = ((x1 >= 0) & (x1 < WW)) ? dx : 0.f;
        __half2 hA = __floats2half2_rn(wy0 * wx0, wy0 * wx1);
        __half2 hB = __floats2half2_rn(wy1 * wx0, wy1 * wx1);
        int y0c = min(max(y0, 0), HH - 1), y1c = min(max(y1, 0), HH - 1);
        int x0c = min(max(x0, 0), WW - 1), x1c = min(max(x1, 0), WW - 1);
        dw0[i] = *(u32*)&hA;
        dw1[i] = *(u32*)&hB;
        dbase[i] = (u32)(y0c * WW + x0c) | ((u32)(x1c - x0c) << 16)
                                         | ((u32)(y1c - y0c) << 17);
    }
    asm volatile("cp.async.wait_group 0;" ::: "memory");
    __syncthreads();                       // desc + wb[0] ready

    // prologue: gather tap 0 into cb[0]
    #pragma unroll
    for (int pass = 0; pass < 4; pass++) {
        int pi = pass * 32 + g;
        uint4 v00, v01, v10, v11; u32 wA, wB;
        gather_issue(xb, dw0, dw1, dbase, 0, pi, cbase, v00, v01, v10, v11, wA, wB);
        gather_combine(cb[0], pi, cbase, v00, v01, v10, v11, wA, wB);
    }
    __syncthreads();

    float acc[8][4];
    #pragma unroll
    for (int i = 0; i < 8; i++)
        #pragma unroll
        for (int j = 0; j < 4; j++) acc[i][j] = 0.f;

    #pragma unroll 1
    for (int t = 0; t < 8; t++) {
        int cur = t & 1, nxt = cur ^ 1;

        stage_w_async(wb[nxt], t + 1, tid);   // weights fly all tap

        #pragma unroll
        for (int pass = 0; pass < 4; pass++) {
            int pi = pass * 32 + g;
            uint4 v00, v01, v10, v11; u32 wA, wB;
            gather_issue(xb, dw0, dw1, dbase, t + 1, pi, cbase,
                         v00, v01, v10, v11, wA, wB);
            mma_ks(cb[cur], wb[cur], acc, pass, cobase, pxh, gid, tig);
            gather_combine(cb[nxt], pi, cbase, v00, v01, v10, v11, wA, wB);
        }

        asm volatile("cp.async.wait_group 0;" ::: "memory");
        __syncthreads();
    }

    // final tap 8: MMA only (cur = 0)
    #pragma unroll
    for (int pass = 0; pass < 4; pass++)
        mma_ks(cb[0], wb[0], acc, pass, cobase, pxh, gid, tig);

    float bl = b_dcn[cobase + gid];
    float bh = b_dcn[cobase + gid + 8];
    float* ob = out + (size_t)b * CO * HW + p0 + pxh + 2 * tig;
    #pragma unroll
    for (int nt = 0; nt < 8; nt++) {
        float2 vlo = make_float2(acc[nt][0] + bl, acc[nt][1] + bl);
        float2 vhi = make_float2(acc[nt][2] + bh, acc[nt][3] + bh);
        *(float2*)(ob + (size_t)(cobase + gid)     * HW + nt * 8) = vlo;
        *(float2*)(ob + (size_t)(cobase + gid + 8) * HW + nt * 8) = vhi;
    }
}

// ---------------------------------------------------------------------------
extern "C" void kernel_launch(void* const* d_in, const int* in_sizes, int n_in,
                              void* d_out, int out_size) {
    const float* x        = (const float*)d_in[0];
    const float* w_offset = (const float*)d_in[1];
    const float* b_offset = (const float*)d_in[2];
    const float* w_dcn    = (const float*)d_in[3];
    const float* b_dcn    = (const float*)d_in[4];
    float* out = (float*)d_out;

    const int SMEM_O = (128 * CSTRH + 32 * CSTRH) * 2;                         // 23040
    const int SMEM_C = (2 * TP * CSTRH + 2 * CO * CSTRH) * 2 + 3 * 9 * TP * 4; // 69120
    cudaFuncSetAttribute(k_offcv, cudaFuncAttributeMaxDynamicSharedMemorySize, SMEM_O);
    cudaFuncSetAttribute(k_dcn,   cudaFuncAttributeMaxDynamicSharedMemorySize, SMEM_C);

    k_transpose<<<dim3(HW / 32, CC / 32, BB), dim3(32, 8)>>>(x);
    k_wreorder<<<(KK * CO * CC + 255) / 256, 256>>>(w_dcn, w_offset);
    k_offcv<<<dim3(HW / 128, BB), 256, SMEM_O>>>(b_offset);
    k_dcn<<<dim3(HW / TP, BB), 256, SMEM_C>>>(b_dcn, out);
}

// round 14
// speedup vs baseline: 2.4204x; 1.0546x over previous
#include <cuda_runtime.h>
#include <cuda_fp16.h>
#include <math.h>

#define BB 8
#define CC 64
#define HH 128
#define WW 128
#define HW (HH*WW)
#define KK 9
#define CO 64
#define CK (CC*KK)   // 576

typedef unsigned int u32;

__device__ __half g_xth[BB*HW*CC];      // x NHWC fp16
__device__ float  g_off[BB*27*HW];      // planar offsets/masks
__device__ __half g_wth[KK*CO*CC];      // dcn weights [t][co][c] fp16
__device__ __half g_woh[KK*32*CC];      // offset weights [t][o pad32][c] fp16

#define CSTRH 72
#define TP 128

__device__ __forceinline__ void cp16(u32 dst_smem, const void* src) {
    asm volatile("cp.async.cg.shared.global [%0], [%1], 16;"
                 :: "r"(dst_smem), "l"(src) : "memory");
}

// ---------------------------------------------------------------------------
// Kernel A: NCHW -> NHWC transpose (fp16 output)
// ---------------------------------------------------------------------------
__global__ void k_transpose(const float* __restrict__ x) {
    __shared__ float tile[32][33];
    int b  = blockIdx.z;
    int p0 = blockIdx.x * 32;
    int c0 = blockIdx.y * 32;
    int tx = threadIdx.x, ty = threadIdx.y;   // 32 x 8
    const float* xb = x + (size_t)b * CC * HW;
    #pragma unroll
    for (int i = 0; i < 32; i += 8)
        tile[ty + i][tx] = xb[(size_t)(c0 + ty + i) * HW + p0 + tx];
    __syncthreads();
    __half* xoh = g_xth + (size_t)b * HW * CC;
    #pragma unroll
    for (int i = 0; i < 32; i += 8)
        xoh[(size_t)(p0 + ty + i) * CC + c0 + tx] = __float2half(tile[tx][ty + i]);
}

// ---------------------------------------------------------------------------
// Kernel W: weight reorder/convert
// ---------------------------------------------------------------------------
__global__ void k_wreorder(const float* __restrict__ wd, const float* __restrict__ wo) {
    int idx = blockIdx.x * 256 + threadIdx.x;
    if (idx < KK * CO * CC) {
        int t  = idx >> 12;
        int co = (idx >> 6) & 63;
        int c  = idx & 63;
        g_wth[idx] = __float2half(wd[co * CK + c * KK + t]);
    }
    if (idx < KK * 32 * CC) {
        int t = idx >> 11;
        int o = (idx >> 6) & 31;
        int c = idx & 63;
        g_woh[idx] = __float2half(o < 27 ? wo[o * CK + c * KK + t] : 0.f);
    }
}

// ---------------------------------------------------------------------------
// Kernel B: offset conv via tensor cores
// ---------------------------------------------------------------------------
__global__ void __launch_bounds__(256, 3) k_offcv(const float* __restrict__ b_off) {
    extern __shared__ __half smh[];
    __half* col = smh;                    // 128 * 72 halves
    __half* wsO = smh + 128 * CSTRH;      // 32 * 72 halves

    int tid = threadIdx.x;
    int b   = blockIdx.y;
    int p0  = blockIdx.x * 128;
    int ho  = blockIdx.x;

    int g = tid >> 3, lane8 = tid & 7, cbase = lane8 * 8;
    const __half* xb = g_xth + (size_t)b * HW * CC;

    int lane = tid & 31, w = tid >> 5;
    int cobase = (w & 1) * 16;
    int pxh    = (w >> 1) * 32;
    int gid = lane >> 2, tig = lane & 3;

    float bl = (cobase + gid     < 27) ? b_off[cobase + gid]     : 0.f;
    float bh = (cobase + gid + 8 < 27) ? b_off[cobase + gid + 8] : 0.f;
    float acc[4][4];
    #pragma unroll
    for (int nt = 0; nt < 4; nt++) {
        acc[nt][0] = bl; acc[nt][1] = bl;
        acc[nt][2] = bh; acc[nt][3] = bh;
    }

    #pragma unroll 1
    for (int t = 0; t < 9; t++) {
        const u32* wsrc = (const u32*)(g_woh + t * 32 * CC);
        #pragma unroll
        for (int idx = tid; idx < 1024; idx += 256) {
            int o = idx >> 5, kp = idx & 31;
            *(u32*)&wsO[o * CSTRH + kp * 2] = wsrc[idx];
        }

        int dty = t / 3 - 1, dtx = t % 3 - 1;
        int y = ho + dty;
        bool vy = (y >= 0) & (y < HH);
        #pragma unroll
        for (int pass = 0; pass < 4; pass++) {
            int pi = pass * 32 + g;
            int xx = pi + dtx;
            uint4 v = make_uint4(0, 0, 0, 0);
            if (vy & (xx >= 0) & (xx < WW))
                v = *(const uint4*)(xb + ((size_t)(y * WW + xx)) * CC + cbase);
            *(uint4*)&col[pi * CSTRH + cbase] = v;
        }
        __syncthreads();

        #pragma unroll
        for (int ks = 0; ks < 4; ks++) {
            int kb = ks * 16 + 2 * tig;
            u32 a0 = *(u32*)&wsO[(cobase + gid)     * CSTRH + kb];
            u32 a1 = *(u32*)&wsO[(cobase + gid + 8) * CSTRH + kb];
            u32 a2 = *(u32*)&wsO[(cobase + gid)     * CSTRH + kb + 8];
            u32 a3 = *(u32*)&wsO[(cobase + gid + 8) * CSTRH + kb + 8];
            #pragma unroll
            for (int nt = 0; nt < 4; nt++) {
                const __half* brow = &col[(pxh + nt * 8 + gid) * CSTRH + kb];
                u32 b0 = *(const u32*)brow;
                u32 b1 = *(const u32*)(brow + 8);
                asm volatile(
                    "mma.sync.aligned.m16n8k16.row.col.f32.f16.f16.f32 "
                    "{%0,%1,%2,%3}, {%4,%5,%6,%7}, {%8,%9}, {%0,%1,%2,%3};"
                    : "+f"(acc[nt][0]), "+f"(acc[nt][1]),
                      "+f"(acc[nt][2]), "+f"(acc[nt][3])
                    : "r"(a0), "r"(a1), "r"(a2), "r"(a3), "r"(b0), "r"(b1));
            }
        }
        __syncthreads();
    }

    float* ob = g_off + (size_t)b * 27 * HW;
    #pragma unroll
    for (int nt = 0; nt < 4; nt++) {
        int wo_lo = pxh + nt * 8 + 2 * tig;
        int p = p0 + wo_lo;
        #pragma unroll
        for (int j = 0; j < 2; j++) {
            int o = cobase + gid + j * 8;
            if (o >= 27) continue;
            float v0 = acc[nt][j * 2], v1 = acc[nt][j * 2 + 1];
            if (o < 9) {
                float a = (float)(ho + o / 3 - 1);
                v0 += a; v1 += a;
            } else if (o < 18) {
                int tt = o - 9;
                float a = (float)(wo_lo + tt % 3 - 1);
                v0 += a; v1 += a + 1.f;
            } else {
                v0 = 1.f / (1.f + __expf(-v0));
                v1 = 1.f / (1.f + __expf(-v1));
            }
            *(float2*)(ob + (size_t)o * HW + p) = make_float2(v0, v1);
        }
    }
}

// ---------------------------------------------------------------------------
// k_dcn helpers
// ---------------------------------------------------------------------------
__device__ __forceinline__ void gather_issue(
        const __half* __restrict__ xb,
        const uint4* __restrict__ dsc,
        int t, int pi, int cbase,
        uint4& v00, uint4& v01, uint4& v10, uint4& v11,
        u32& wA, u32& wB) {
    uint4 d = dsc[t * TP + pi];           // one LDS.128
    wA = d.x;
    wB = d.y;
    int p00 = d.z & 0x3FFF;
    int dxc = (d.z >> 16) & 1;
    int dyc = (d.z >> 17) & 1;
    const __half* b00 = xb + (size_t)p00 * CC + cbase;
    v00 = *(const uint4*)b00;
    v01 = *(const uint4*)(b00 + dxc * CC);
    v10 = *(const uint4*)(b00 + dyc * (WW * CC));
    v11 = *(const uint4*)(b00 + dyc * (WW * CC) + dxc * CC);
}

__device__ __forceinline__ void gather_combine(
        __half* __restrict__ cbuf, int pi, int cbase,
        const uint4& v00, const uint4& v01, const uint4& v10, const uint4& v11,
        u32 wA, u32 wB) {
    __half2 hAp = *(const __half2*)&wA;   // (w00, w01)
    __half2 hBp = *(const __half2*)&wB;   // (w10, w11)
    __half2 w00b = __low2half2(hAp),  w01b = __high2half2(hAp);
    __half2 w10b = __low2half2(hBp),  w11b = __high2half2(hBp);
    const __half2* h00 = (const __half2*)&v00;
    const __half2* h01 = (const __half2*)&v01;
    const __half2* h10 = (const __half2*)&v10;
    const __half2* h11 = (const __half2*)&v11;
    __half2 hh[4];
    #pragma unroll
    for (int q = 0; q < 4; q++) {
        __half2 r = __hmul2(w11b, h11[q]);
        r = __hfma2(w10b, h10[q], r);
        r = __hfma2(w01b, h01[q], r);
        hh[q] = __hfma2(w00b, h00[q], r);
    }
    *(uint4*)&cbuf[pi * CSTRH + cbase] = *(uint4*)hh;
}

__device__ __forceinline__ void mma_ks(
        const __half* __restrict__ col, const __half* __restrict__ wsT,
        float (&acc)[8][4], int ks, int cobase, int pxh, int gid, int tig) {
    int kb = ks * 16 + 2 * tig;
    u32 a0 = *(const u32*)&wsT[(cobase + gid)     * CSTRH + kb];
    u32 a1 = *(const u32*)&wsT[(cobase + gid + 8) * CSTRH + kb];
    u32 a2 = *(const u32*)&wsT[(cobase + gid)     * CSTRH + kb + 8];
    u32 a3 = *(const u32*)&wsT[(cobase + gid + 8) * CSTRH + kb + 8];
    #pragma unroll
    for (int nt = 0; nt < 8; nt++) {
        const __half* brow = &col[(pxh + nt * 8 + gid) * CSTRH + kb];
        u32 b0 = *(const u32*)brow;
        u32 b1 = *(const u32*)(brow + 8);
        asm volatile(
            "mma.sync.aligned.m16n8k16.row.col.f32.f16.f16.f32 "
            "{%0,%1,%2,%3}, {%4,%5,%6,%7}, {%8,%9}, {%0,%1,%2,%3};"
            : "+f"(acc[nt][0]), "+f"(acc[nt][1]),
              "+f"(acc[nt][2]), "+f"(acc[nt][3])
            : "r"(a0), "r"(a1), "r"(a2), "r"(a3), "r"(b0), "r"(b1));
    }
}

__device__ __forceinline__ void stage_w_async(__half* wbuf, int t, int tid) {
    u32 wbs = (u32)__cvta_generic_to_shared(wbuf);
    const __half* wsrc = g_wth + t * CO * CC;
    #pragma unroll
    for (int i = 0; i < 2; i++) {
        int idx = i * 256 + tid;          // 0..511
        int co = idx >> 3, kp8 = idx & 7; // 16B = 8 halves per cp
        cp16(wbs + (co * CSTRH + kp8 * 8) * 2, wsrc + co * CC + kp8 * 8);
    }
    asm volatile("cp.async.commit_group;" ::: "memory");
}

// ---------------------------------------------------------------------------
// Kernel C: fused gather+GEMM, intra-tap interleaved; uint4 descriptors +
// fp16x2 bilinear combine.
// ---------------------------------------------------------------------------
__global__ void __launch_bounds__(256, 3) k_dcn(const float* __restrict__ b_dcn,
                                                float* __restrict__ out) {
    extern __shared__ __half smh[];
    __half* cb[2] = { smh, smh + TP * CSTRH };
    __half* wb[2] = { smh + 2 * TP * CSTRH, smh + 2 * TP * CSTRH + CO * CSTRH };
    uint4* dsc = (uint4*)(smh + 2 * TP * CSTRH + 2 * CO * CSTRH);  // [9*TP]

    int tid = threadIdx.x;
    int b   = blockIdx.y;
    int p0  = blockIdx.x * TP;

    int g = tid >> 3, lane8 = tid & 7, cbase = lane8 * 8;
    const __half* xb = g_xth + (size_t)b * HW * CC;
    const float* offb = g_off + (size_t)b * 27 * HW;

    int lane = tid & 31, w = tid >> 5;
    int cobase = (w & 3) * 16;
    int pxh    = (w >> 2) * 64;
    int gid = lane >> 2, tig = lane & 3;

    stage_w_async(wb[0], 0, tid);

    // cooperative descriptor precompute: 1152 items, no per-lane redundancy
    #pragma unroll
    for (int i = tid; i < 9 * TP; i += 256) {
        int t = i >> 7, pi = i & 127;
        float py  = offb[(size_t)t * HW + p0 + pi];
        float pxs = offb[(size_t)(9 + t) * HW + p0 + pi];
        float mm  = offb[(size_t)(18 + t) * HW + p0 + pi];
        float y0f = floorf(py), x0f = floorf(pxs);
        float dy = py - y0f, dx = pxs - x0f;
        int y0 = (int)y0f, x0 = (int)x0f;
        int y1 = y0 + 1,  x1 = x0 + 1;
        float wy0 = ((y0 >= 0) & (y0 < HH)) ? (1.f - dy) * mm : 0.f;
        float wy1 = ((y1 >= 0) & (y1 < HH)) ? dy * mm : 0.f;
        float wx0 = ((x0 >= 0) & (x0 < WW)) ? (1.f - dx) : 0.f;
        float wx1 = ((x1 >= 0) & (x1 < WW)) ? dx : 0.f;
        __half2 hA = __floats2half2_rn(wy0 * wx0, wy0 * wx1);
        __half2 hB = __floats2half2_rn(wy1 * wx0, wy1 * wx1);
        int y0c = min(max(y0, 0), HH - 1), y1c = min(max(y1, 0), HH - 1);
        int x0c = min(max(x0, 0), WW - 1), x1c = min(max(x1, 0), WW - 1);
        u32 pk = (u32)(y0c * WW + x0c) | ((u32)(x1c - x0c) << 16)
                                       | ((u32)(y1c - y0c) << 17);
        dsc[i] = make_uint4(*(u32*)&hA, *(u32*)&hB, pk, 0u);
    }
    asm volatile("cp.async.wait_group 0;" ::: "memory");
    __syncthreads();                       // desc + wb[0] ready

    // prologue: gather tap 0 into cb[0]
    #pragma unroll
    for (int pass = 0; pass < 4; pass++) {
        int pi = pass * 32 + g;
        uint4 v00, v01, v10, v11; u32 wA, wB;
        gather_issue(xb, dsc, 0, pi, cbase, v00, v01, v10, v11, wA, wB);
        gather_combine(cb[0], pi, cbase, v00, v01, v10, v11, wA, wB);
    }
    __syncthreads();

    float acc[8][4];
    #pragma unroll
    for (int i = 0; i < 8; i++)
        #pragma unroll
        for (int j = 0; j < 4; j++) acc[i][j] = 0.f;

    #pragma unroll 1
    for (int t = 0; t < 8; t++) {
        int cur = t & 1, nxt = cur ^ 1;

        stage_w_async(wb[nxt], t + 1, tid);   // weights fly all tap

        #pragma unroll
        for (int pass = 0; pass < 4; pass++) {
            int pi = pass * 32 + g;
            uint4 v00, v01, v10, v11; u32 wA, wB;
            gather_issue(xb, dsc, t + 1, pi, cbase,
                         v00, v01, v10, v11, wA, wB);
            mma_ks(cb[cur], wb[cur], acc, pass, cobase, pxh, gid, tig);
            gather_combine(cb[nxt], pi, cbase, v00, v01, v10, v11, wA, wB);
        }

        asm volatile("cp.async.wait_group 0;" ::: "memory");
        __syncthreads();
    }

    // final tap 8: MMA only (cur = 0)
    #pragma unroll
    for (int pass = 0; pass < 4; pass++)
        mma_ks(cb[0], wb[0], acc, pass, cobase, pxh, gid, tig);

    float bl = b_dcn[cobase + gid];
    float bh = b_dcn[cobase + gid + 8];
    float* ob = out + (size_t)b * CO * HW + p0 + pxh + 2 * tig;
    #pragma unroll
    for (int nt = 0; nt < 8; nt++) {
        float2 vlo = make_float2(acc[nt][0] + bl, acc[nt][1] + bl);
        float2 vhi = make_float2(acc[nt][2] + bh, acc[nt][3] + bh);
        *(float2*)(ob + (size_t)(cobase + gid)     * HW + nt * 8) = vlo;
        *(float2*)(ob + (size_t)(cobase + gid + 8) * HW + nt * 8) = vhi;
    }
}

// ---------------------------------------------------------------------------
extern "C" void kernel_launch(void* const* d_in, const int* in_sizes, int n_in,
                              void* d_out, int out_size) {
    const float* x        = (const float*)d_in[0];
    const float* w_offset = (const float*)d_in[1];
    const float* b_offset = (const float*)d_in[2];
    const float* w_dcn    = (const float*)d_in[3];
    const float* b_dcn    = (const float*)d_in[4];
    float* out = (float*)d_out;

    const int SMEM_O = (128 * CSTRH + 32 * CSTRH) * 2;                        // 23040
    const int SMEM_C = (2 * TP * CSTRH + 2 * CO * CSTRH) * 2 + 9 * TP * 16;   // 73728
    cudaFuncSetAttribute(k_offcv, cudaFuncAttributeMaxDynamicSharedMemorySize, SMEM_O);
    cudaFuncSetAttribute(k_dcn,   cudaFuncAttributeMaxDynamicSharedMemorySize, SMEM_C);

    k_transpose<<<dim3(HW / 32, CC / 32, BB), dim3(32, 8)>>>(x);
    k_wreorder<<<(KK * CO * CC + 255) / 256, 256>>>(w_dcn, w_offset);
    k_offcv<<<dim3(HW / 128, BB), 256, SMEM_O>>>(b_offset);
    k_dcn<<<dim3(HW / TP, BB), 256, SMEM_C>>>(b_dcn, out);
}

// round 15
// speedup vs baseline: 2.5844x; 1.0678x over previous
#include <cuda_runtime.h>
#include <cuda_fp16.h>
#include <math.h>

#define BB 8
#define CC 64
#define HH 128
#define WW 128
#define HW (HH*WW)
#define KK 9
#define CO 64
#define CK (CC*KK)   // 576

typedef unsigned int u32;

__device__ __half g_xth[BB*HW*CC];      // x NHWC fp16
__device__ float  g_off[BB*27*HW];      // planar offsets/masks
__device__ __half g_wth[KK*CO*CC];      // dcn weights [t][co][c] fp16
__device__ __half g_woh[KK*32*CC];      // offset weights [t][o pad32][c] fp16

#define CSTRH 72
#define TP 128

__device__ __forceinline__ void cp16(u32 dst_smem, const void* src) {
    asm volatile("cp.async.cg.shared.global [%0], [%1], 16;"
                 :: "r"(dst_smem), "l"(src) : "memory");
}

// ---------------------------------------------------------------------------
// Kernel A: NCHW -> NHWC transpose (fp16 output)
// ---------------------------------------------------------------------------
__global__ void k_transpose(const float* __restrict__ x) {
    __shared__ float tile[32][33];
    int b  = blockIdx.z;
    int p0 = blockIdx.x * 32;
    int c0 = blockIdx.y * 32;
    int tx = threadIdx.x, ty = threadIdx.y;   // 32 x 8
    const float* xb = x + (size_t)b * CC * HW;
    #pragma unroll
    for (int i = 0; i < 32; i += 8)
        tile[ty + i][tx] = xb[(size_t)(c0 + ty + i) * HW + p0 + tx];
    __syncthreads();
    __half* xoh = g_xth + (size_t)b * HW * CC;
    #pragma unroll
    for (int i = 0; i < 32; i += 8)
        xoh[(size_t)(p0 + ty + i) * CC + c0 + tx] = __float2half(tile[tx][ty + i]);
}

// ---------------------------------------------------------------------------
// Kernel W: weight reorder/convert
// ---------------------------------------------------------------------------
__global__ void k_wreorder(const float* __restrict__ wd, const float* __restrict__ wo) {
    int idx = blockIdx.x * 256 + threadIdx.x;
    if (idx < KK * CO * CC) {
        int t  = idx >> 12;
        int co = (idx >> 6) & 63;
        int c  = idx & 63;
        g_wth[idx] = __float2half(wd[co * CK + c * KK + t]);
    }
    if (idx < KK * 32 * CC) {
        int t = idx >> 11;
        int o = (idx >> 6) & 31;
        int c = idx & 63;
        g_woh[idx] = __float2half(o < 27 ? wo[o * CK + c * KK + t] : 0.f);
    }
}

// ---------------------------------------------------------------------------
// Kernel B: offset conv via tensor cores
// ---------------------------------------------------------------------------
__global__ void __launch_bounds__(256, 3) k_offcv(const float* __restrict__ b_off) {
    extern __shared__ __half smh[];
    __half* col = smh;                    // 128 * 72 halves
    __half* wsO = smh + 128 * CSTRH;      // 32 * 72 halves

    int tid = threadIdx.x;
    int b   = blockIdx.y;
    int p0  = blockIdx.x * 128;
    int ho  = blockIdx.x;

    int g = tid >> 3, lane8 = tid & 7, cbase = lane8 * 8;
    const __half* xb = g_xth + (size_t)b * HW * CC;

    int lane = tid & 31, w = tid >> 5;
    int cobase = (w & 1) * 16;
    int pxh    = (w >> 1) * 32;
    int gid = lane >> 2, tig = lane & 3;

    float bl = (cobase + gid     < 27) ? b_off[cobase + gid]     : 0.f;
    float bh = (cobase + gid + 8 < 27) ? b_off[cobase + gid + 8] : 0.f;
    float acc[4][4];
    #pragma unroll
    for (int nt = 0; nt < 4; nt++) {
        acc[nt][0] = bl; acc[nt][1] = bl;
        acc[nt][2] = bh; acc[nt][3] = bh;
    }

    #pragma unroll 1
    for (int t = 0; t < 9; t++) {
        const u32* wsrc = (const u32*)(g_woh + t * 32 * CC);
        #pragma unroll
        for (int idx = tid; idx < 1024; idx += 256) {
            int o = idx >> 5, kp = idx & 31;
            *(u32*)&wsO[o * CSTRH + kp * 2] = wsrc[idx];
        }

        int dty = t / 3 - 1, dtx = t % 3 - 1;
        int y = ho + dty;
        bool vy = (y >= 0) & (y < HH);
        #pragma unroll
        for (int pass = 0; pass < 4; pass++) {
            int pi = pass * 32 + g;
            int xx = pi + dtx;
            uint4 v = make_uint4(0, 0, 0, 0);
            if (vy & (xx >= 0) & (xx < WW))
                v = *(const uint4*)(xb + ((size_t)(y * WW + xx)) * CC + cbase);
            *(uint4*)&col[pi * CSTRH + cbase] = v;
        }
        __syncthreads();

        #pragma unroll
        for (int ks = 0; ks < 4; ks++) {
            int kb = ks * 16 + 2 * tig;
            u32 a0 = *(u32*)&wsO[(cobase + gid)     * CSTRH + kb];
            u32 a1 = *(u32*)&wsO[(cobase + gid + 8) * CSTRH + kb];
            u32 a2 = *(u32*)&wsO[(cobase + gid)     * CSTRH + kb + 8];
            u32 a3 = *(u32*)&wsO[(cobase + gid + 8) * CSTRH + kb + 8];
            #pragma unroll
            for (int nt = 0; nt < 4; nt++) {
                const __half* brow = &col[(pxh + nt * 8 + gid) * CSTRH + kb];
                u32 b0 = *(const u32*)brow;
                u32 b1 = *(const u32*)(brow + 8);
                asm volatile(
                    "mma.sync.aligned.m16n8k16.row.col.f32.f16.f16.f32 "
                    "{%0,%1,%2,%3}, {%4,%5,%6,%7}, {%8,%9}, {%0,%1,%2,%3};"
                    : "+f"(acc[nt][0]), "+f"(acc[nt][1]),
                      "+f"(acc[nt][2]), "+f"(acc[nt][3])
                    : "r"(a0), "r"(a1), "r"(a2), "r"(a3), "r"(b0), "r"(b1));
            }
        }
        __syncthreads();
    }

    float* ob = g_off + (size_t)b * 27 * HW;
    #pragma unroll
    for (int nt = 0; nt < 4; nt++) {
        int wo_lo = pxh + nt * 8 + 2 * tig;
        int p = p0 + wo_lo;
        #pragma unroll
        for (int j = 0; j < 2; j++) {
            int o = cobase + gid + j * 8;
            if (o >= 27) continue;
            float v0 = acc[nt][j * 2], v1 = acc[nt][j * 2 + 1];
            if (o < 9) {
                float a = (float)(ho + o / 3 - 1);
                v0 += a; v1 += a;
            } else if (o < 18) {
                int tt = o - 9;
                float a = (float)(wo_lo + tt % 3 - 1);
                v0 += a; v1 += a + 1.f;
            } else {
                v0 = 1.f / (1.f + __expf(-v0));
                v1 = 1.f / (1.f + __expf(-v1));
            }
            *(float2*)(ob + (size_t)o * HW + p) = make_float2(v0, v1);
        }
    }
}

// ---------------------------------------------------------------------------
// k_dcn helpers
// ---------------------------------------------------------------------------
__device__ __forceinline__ void gather_issue(
        const __half* __restrict__ xb,
        const uint4* __restrict__ dsc,
        int t, int pi, int cbase,
        uint4& v00, uint4& v01, uint4& v10, uint4& v11,
        u32& wA, u32& wB) {
    uint4 d = dsc[t * TP + pi];           // one LDS.128
    wA = d.x;
    wB = d.y;
    int p00 = d.z & 0x3FFF;
    int dxc = (d.z >> 16) & 1;
    int dyc = (d.z >> 17) & 1;
    const __half* b00 = xb + (size_t)p00 * CC + cbase;
    v00 = *(const uint4*)b00;
    v01 = *(const uint4*)(b00 + dxc * CC);
    v10 = *(const uint4*)(b00 + dyc * (WW * CC));
    v11 = *(const uint4*)(b00 + dyc * (WW * CC) + dxc * CC);
}

__device__ __forceinline__ void gather_combine(
        __half* __restrict__ cbuf, int pi, int cbase,
        const uint4& v00, const uint4& v01, const uint4& v10, const uint4& v11,
        u32 wA, u32 wB) {
    __half2 hAp = *(const __half2*)&wA;   // (w00, w01)
    __half2 hBp = *(const __half2*)&wB;   // (w10, w11)
    __half2 w00b = __low2half2(hAp),  w01b = __high2half2(hAp);
    __half2 w10b = __low2half2(hBp),  w11b = __high2half2(hBp);
    const __half2* h00 = (const __half2*)&v00;
    const __half2* h01 = (const __half2*)&v01;
    const __half2* h10 = (const __half2*)&v10;
    const __half2* h11 = (const __half2*)&v11;
    __half2 hh[4];
    #pragma unroll
    for (int q = 0; q < 4; q++) {
        __half2 r = __hmul2(w11b, h11[q]);
        r = __hfma2(w10b, h10[q], r);
        r = __hfma2(w01b, h01[q], r);
        hh[q] = __hfma2(w00b, h00[q], r);
    }
    *(uint4*)&cbuf[pi * CSTRH + cbase] = *(uint4*)hh;
}

// square warp tile: 32co x 32px, 2 co-tiles x 4 n-tiles, B frags shared
__device__ __forceinline__ void mma_ks(
        const __half* __restrict__ col, const __half* __restrict__ wsT,
        float (&acc)[2][4][4], int ks, int cobase, int pxh, int gid, int tig) {
    int kb = ks * 16 + 2 * tig;
    u32 a[2][4];
    #pragma unroll
    for (int ct = 0; ct < 2; ct++) {
        int cb0 = cobase + ct * 16;
        a[ct][0] = *(const u32*)&wsT[(cb0 + gid)     * CSTRH + kb];
        a[ct][1] = *(const u32*)&wsT[(cb0 + gid + 8) * CSTRH + kb];
        a[ct][2] = *(const u32*)&wsT[(cb0 + gid)     * CSTRH + kb + 8];
        a[ct][3] = *(const u32*)&wsT[(cb0 + gid + 8) * CSTRH + kb + 8];
    }
    #pragma unroll
    for (int nt = 0; nt < 4; nt++) {
        const __half* brow = &col[(pxh + nt * 8 + gid) * CSTRH + kb];
        u32 b0 = *(const u32*)brow;
        u32 b1 = *(const u32*)(brow + 8);
        #pragma unroll
        for (int ct = 0; ct < 2; ct++) {
            asm volatile(
                "mma.sync.aligned.m16n8k16.row.col.f32.f16.f16.f32 "
                "{%0,%1,%2,%3}, {%4,%5,%6,%7}, {%8,%9}, {%0,%1,%2,%3};"
                : "+f"(acc[ct][nt][0]), "+f"(acc[ct][nt][1]),
                  "+f"(acc[ct][nt][2]), "+f"(acc[ct][nt][3])
                : "r"(a[ct][0]), "r"(a[ct][1]), "r"(a[ct][2]), "r"(a[ct][3]),
                  "r"(b0), "r"(b1));
        }
    }
}

__device__ __forceinline__ void stage_w_async(__half* wbuf, int t, int tid) {
    u32 wbs = (u32)__cvta_generic_to_shared(wbuf);
    const __half* wsrc = g_wth + t * CO * CC;
    #pragma unroll
    for (int i = 0; i < 2; i++) {
        int idx = i * 256 + tid;          // 0..511
        int co = idx >> 3, kp8 = idx & 7; // 16B = 8 halves per cp
        cp16(wbs + (co * CSTRH + kp8 * 8) * 2, wsrc + co * CC + kp8 * 8);
    }
    asm volatile("cp.async.commit_group;" ::: "memory");
}

// ---------------------------------------------------------------------------
// Kernel C: fused gather+GEMM, intra-tap interleaved; square 32x32 warp tiles
// ---------------------------------------------------------------------------
__global__ void __launch_bounds__(256, 3) k_dcn(const float* __restrict__ b_dcn,
                                                float* __restrict__ out) {
    extern __shared__ __half smh[];
    __half* cb[2] = { smh, smh + TP * CSTRH };
    __half* wb[2] = { smh + 2 * TP * CSTRH, smh + 2 * TP * CSTRH + CO * CSTRH };
    uint4* dsc = (uint4*)(smh + 2 * TP * CSTRH + 2 * CO * CSTRH);  // [9*TP]

    int tid = threadIdx.x;
    int b   = blockIdx.y;
    int p0  = blockIdx.x * TP;

    int g = tid >> 3, lane8 = tid & 7, cbase = lane8 * 8;
    const __half* xb = g_xth + (size_t)b * HW * CC;
    const float* offb = g_off + (size_t)b * 27 * HW;

    int lane = tid & 31, w = tid >> 5;
    int cobase = (w & 1) * 32;            // 2 co-groups of 32
    int pxh    = (w >> 1) * 32;           // 4 px-groups of 32
    int gid = lane >> 2, tig = lane & 3;

    stage_w_async(wb[0], 0, tid);

    // cooperative descriptor precompute
    #pragma unroll
    for (int i = tid; i < 9 * TP; i += 256) {
        int t = i >> 7, pi = i & 127;
        float py  = offb[(size_t)t * HW + p0 + pi];
        float pxs = offb[(size_t)(9 + t) * HW + p0 + pi];
        float mm  = offb[(size_t)(18 + t) * HW + p0 + pi];
        float y0f = floorf(py), x0f = floorf(pxs);
        float dy = py - y0f, dx = pxs - x0f;
        int y0 = (int)y0f, x0 = (int)x0f;
        int y1 = y0 + 1,  x1 = x0 + 1;
        float wy0 = ((y0 >= 0) & (y0 < HH)) ? (1.f - dy) * mm : 0.f;
        float wy1 = ((y1 >= 0) & (y1 < HH)) ? dy * mm : 0.f;
        float wx0 = ((x0 >= 0) & (x0 < WW)) ? (1.f - dx) : 0.f;
        float wx1 = ((x1 >= 0) & (x1 < WW)) ? dx : 0.f;
        __half2 hA = __floats2half2_rn(wy0 * wx0, wy0 * wx1);
        __half2 hB = __floats2half2_rn(wy1 * wx0, wy1 * wx1);
        int y0c = min(max(y0, 0), HH - 1), y1c = min(max(y1, 0), HH - 1);
        int x0c = min(max(x0, 0), WW - 1), x1c = min(max(x1, 0), WW - 1);
        u32 pk = (u32)(y0c * WW + x0c) | ((u32)(x1c - x0c) << 16)
                                       | ((u32)(y1c - y0c) << 17);
        dsc[i] = make_uint4(*(u32*)&hA, *(u32*)&hB, pk, 0u);
    }
    asm volatile("cp.async.wait_group 0;" ::: "memory");
    __syncthreads();

    // prologue: gather tap 0 into cb[0]
    #pragma unroll
    for (int pass = 0; pass < 4; pass++) {
        int pi = pass * 32 + g;
        uint4 v00, v01, v10, v11; u32 wA, wB;
        gather_issue(xb, dsc, 0, pi, cbase, v00, v01, v10, v11, wA, wB);
        gather_combine(cb[0], pi, cbase, v00, v01, v10, v11, wA, wB);
    }
    __syncthreads();

    float acc[2][4][4];
    #pragma unroll
    for (int c = 0; c < 2; c++)
        #pragma unroll
        for (int i = 0; i < 4; i++)
            #pragma unroll
            for (int j = 0; j < 4; j++) acc[c][i][j] = 0.f;

    #pragma unroll 1
    for (int t = 0; t < 8; t++) {
        int cur = t & 1, nxt = cur ^ 1;

        stage_w_async(wb[nxt], t + 1, tid);

        #pragma unroll
        for (int pass = 0; pass < 4; pass++) {
            int pi = pass * 32 + g;
            uint4 v00, v01, v10, v11; u32 wA, wB;
            gather_issue(xb, dsc, t + 1, pi, cbase,
                         v00, v01, v10, v11, wA, wB);
            mma_ks(cb[cur], wb[cur], acc, pass, cobase, pxh, gid, tig);
            gather_combine(cb[nxt], pi, cbase, v00, v01, v10, v11, wA, wB);
        }

        asm volatile("cp.async.wait_group 0;" ::: "memory");
        __syncthreads();
    }

    // final tap 8: MMA only
    #pragma unroll
    for (int pass = 0; pass < 4; pass++)
        mma_ks(cb[0], wb[0], acc, pass, cobase, pxh, gid, tig);

    // epilogue: 2 co-tiles x 4 n-tiles
    float* ob = out + (size_t)b * CO * HW + p0 + pxh + 2 * tig;
    #pragma unroll
    for (int ct = 0; ct < 2; ct++) {
        int co_lo = cobase + ct * 16 + gid;
        float bl = b_dcn[co_lo];
        float bh = b_dcn[co_lo + 8];
        #pragma unroll
        for (int nt = 0; nt < 4; nt++) {
            float2 vlo = make_float2(acc[ct][nt][0] + bl, acc[ct][nt][1] + bl);
            float2 vhi = make_float2(acc[ct][nt][2] + bh, acc[ct][nt][3] + bh);
            *(float2*)(ob + (size_t)co_lo       * HW + nt * 8) = vlo;
            *(float2*)(ob + (size_t)(co_lo + 8) * HW + nt * 8) = vhi;
        }
    }
}

// ---------------------------------------------------------------------------
extern "C" void kernel_launch(void* const* d_in, const int* in_sizes, int n_in,
                              void* d_out, int out_size) {
    const float* x        = (const float*)d_in[0];
    const float* w_offset = (const float*)d_in[1];
    const float* b_offset = (const float*)d_in[2];
    const float* w_dcn    = (const float*)d_in[3];
    const float* b_dcn    = (const float*)d_in[4];
    float* out = (float*)d_out;

    const int SMEM_O = (128 * CSTRH + 32 * CSTRH) * 2;                        // 23040
    const int SMEM_C = (2 * TP * CSTRH + 2 * CO * CSTRH) * 2 + 9 * TP * 16;   // 73728
    cudaFuncSetAttribute(k_offcv, cudaFuncAttributeMaxDynamicSharedMemorySize, SMEM_O);
    cudaFuncSetAttribute(k_dcn,   cudaFuncAttributeMaxDynamicSharedMemorySize, SMEM_C);

    k_transpose<<<dim3(HW / 32, CC / 32, BB), dim3(32, 8)>>>(x);
    k_wreorder<<<(KK * CO * CC + 255) / 256, 256>>>(w_dcn, w_offset);
    k_offcv<<<dim3(HW / 128, BB), 256, SMEM_O>>>(b_offset);
    k_dcn<<<dim3(HW / TP, BB), 256, SMEM_C>>>(b_dcn, out);
}